// round 9
// baseline (speedup 1.0000x reference)
#include <cuda_runtime.h>

// Output = sigmoid(2.0) everywhere (reference's s = exp(y-y) == 1).
// 64 MiB fp32 constant fill at the LTS write wall (~5.7 TB/s measured across
// STG.128 / bulk-async / hybrid). Last structural lever: Blackwell 256-bit
// stores (st.global.v8.f32) — same bytes, half the store instructions and
// half the L1tex store-wavefront slots per byte (L1 was the hottest counter
// at 61.7%). 4 x STG.256 per thread = 128 B/thread, 2048 blocks x 256 thr.
// (Resubmission of R7 kernel — R8 bench was an infra failure, no signal.)

static constexpr int THREADS = 256;
static constexpr int V8_PER_THREAD = 4;   // 4 x 32 B = 128 B per thread

__global__ void __launch_bounds__(THREADS) fill_sigmoid2_v256(float* __restrict__ out) {
    const float v = 0.8807970779778823f;  // sigmoid(2.0)
    // Index in 32-byte (float8) units. Total float8s = 2,097,152 -> 32-bit safe.
    unsigned base8 = blockIdx.x * (THREADS * V8_PER_THREAD) + threadIdx.x;
    float* p = out + (size_t)base8 * 8;
#pragma unroll
    for (int k = 0; k < V8_PER_THREAD; k++) {
        // 256-bit store: 8 consecutive fp32, 32B-aligned (d_out is 256B-aligned,
        // offsets are multiples of 32B). Warp writes 1024B contiguous per op.
        asm volatile(
            "st.global.v8.f32 [%0], {%1, %1, %1, %1, %1, %1, %1, %1};"
            :: "l"(p + (size_t)k * (THREADS * 8)), "f"(v)
            : "memory");
    }
}

__global__ void fill_sigmoid2_tail(float* __restrict__ out, int start, int n) {
    int i = start + blockIdx.x * blockDim.x + threadIdx.x;
    if (i < n) out[i] = 0.8807970779778823f;
}

extern "C" void kernel_launch(void* const* d_in, const int* in_sizes, int n_in,
                              void* d_out, int out_size) {
    (void)d_in; (void)in_sizes; (void)n_in;
    float* out = (float*)d_out;

    const int elems_per_block = THREADS * V8_PER_THREAD * 8;  // 8192 fp32 = 32 KB
    int blocks = out_size / elems_per_block;                  // 2048 exact
    int covered = blocks * elems_per_block;

    if (blocks > 0) {
        fill_sigmoid2_v256<<<blocks, THREADS>>>(out);
    }
    int rem = out_size - covered;                             // 0 for this shape
    if (rem > 0) {
        int t = 256;
        int b = (rem + t - 1) / t;
        fill_sigmoid2_tail<<<b, t>>>(out, covered, out_size);
    }
}